// round 5
// baseline (speedup 1.0000x reference)
#include <cuda_runtime.h>
#include <cuda_bf16.h>
#include <cstdint>
#include <cstddef>

#define N_NODES 50000
#define E_EDGES 600000
#define E_LABEL 200000
#define HD 128
#define FIN 768
#define NLAYERS 4
#define PAD_ROWS 50048              // 391 * 128 (sq region padded)
#define TOT_ROWS (2 * PAD_ROWS)     // 100096
#define LDA2 256                    // layer A-plane leading dim (agg cols 0-127, root cols 128-255)
#define MQ_OFF PAD_ROWS
#define W_LIN_ELEMS (HD * FIN)                   // 98304
#define W_LAYER_ELEMS (HD * 256)                 // 32768 per (layer,dir)
#define W_TOT (W_LIN_ELEMS + NLAYERS * 2 * W_LAYER_ELEMS)

// ---------------- device scratch ----------------
__device__ float g_xmq[2 * (size_t)N_NODES * HD];
__device__ float g_xsq[2 * (size_t)N_NODES * HD];
__device__ __nv_bfloat16 g_Ah[2 * (size_t)TOT_ROWS * LDA2];
__device__ __nv_bfloat16 g_Al[2 * (size_t)TOT_ROWS * LDA2];
__device__ __nv_bfloat16 g_sqxh[(size_t)N_NODES * FIN];
__device__ __nv_bfloat16 g_sqxl[(size_t)N_NODES * FIN];
__device__ __nv_bfloat16 g_wh[W_TOT];
__device__ __nv_bfloat16 g_wl[W_TOT];
__device__ int g_cnt_sq[N_NODES];
__device__ int g_cnt_mq[N_NODES];
__device__ int g_rp_sq[N_NODES + 1];
__device__ int g_rp_mq[N_NODES + 1];
__device__ int g_cur_sq[N_NODES];
__device__ int g_cur_mq[N_NODES];
__device__ int g_col_sq[E_EDGES];
__device__ int g_col_mq[E_EDGES];

// ================= helpers =================
__device__ __forceinline__ uint32_t smem_u32(const void* p) {
    uint32_t a;
    asm("{ .reg .u64 t; cvta.to.shared.u64 t, %1; cvt.u32.u64 %0, t; }" : "=r"(a) : "l"(p));
    return a;
}
__device__ __forceinline__ void ldsm_x4(uint32_t* r, uint32_t addr) {
    asm volatile("ldmatrix.sync.aligned.m8n8.x4.shared.b16 {%0,%1,%2,%3}, [%4];"
                 : "=r"(r[0]), "=r"(r[1]), "=r"(r[2]), "=r"(r[3]) : "r"(addr));
}
__device__ __forceinline__ void mma_bf16(float* d, const uint32_t* a, uint32_t b0, uint32_t b1) {
    asm volatile(
        "mma.sync.aligned.m16n8k16.row.col.f32.bf16.bf16.f32 "
        "{%0,%1,%2,%3},{%4,%5,%6,%7},{%8,%9},{%0,%1,%2,%3};"
        : "+f"(d[0]), "+f"(d[1]), "+f"(d[2]), "+f"(d[3])
        : "r"(a[0]), "r"(a[1]), "r"(a[2]), "r"(a[3]), "r"(b0), "r"(b1));
}
__device__ __forceinline__ uint32_t pack_bf2(float a, float b) {
    __nv_bfloat162 h = __floats2bfloat162_rn(a, b);
    return *reinterpret_cast<uint32_t*>(&h);
}
__device__ __forceinline__ void cp16(uint32_t dst, const void* src, uint32_t bytes) {
    asm volatile("cp.async.cg.shared.global [%0], [%1], 16, %2;"
                 :: "r"(dst), "l"(src), "r"(bytes));
}
#define CP_COMMIT() asm volatile("cp.async.commit_group;" ::: "memory")
#define CP_WAIT1() asm volatile("cp.async.wait_group 1;" ::: "memory")
#define CP_WAIT0() asm volatile("cp.async.wait_group 0;" ::: "memory")

// ---------------- CSR build ----------------
__global__ void count_edges(const int* __restrict__ src, const int* __restrict__ dst,
                            int* __restrict__ cnt_sq, int* __restrict__ cnt_mq) {
    int e = blockIdx.x * blockDim.x + threadIdx.x;
    if (e < E_EDGES) {
        atomicAdd(&cnt_sq[dst[e]], 1);
        atomicAdd(&cnt_mq[src[e]], 1);
    }
}

__global__ void scan2(const int* __restrict__ cntA, int* __restrict__ rpA, int* __restrict__ curA,
                      const int* __restrict__ cntB, int* __restrict__ rpB, int* __restrict__ curB) {
    const int* cnt = blockIdx.x ? cntB : cntA;
    int* rp  = blockIdx.x ? rpB  : rpA;
    int* cur = blockIdx.x ? curB : curA;
    const int n = N_NODES;
    __shared__ int wsum[32];
    int tid = threadIdx.x, lane = tid & 31, w = tid >> 5;
    int base = 0;
    for (int s = 0; s < n; s += 1024) {
        int i = s + tid;
        int v = (i < n) ? cnt[i] : 0;
        int x = v;
#pragma unroll
        for (int o = 1; o < 32; o <<= 1) {
            int t = __shfl_up_sync(0xffffffffu, x, o);
            if (lane >= o) x += t;
        }
        if (lane == 31) wsum[w] = x;
        __syncthreads();
        if (w == 0) {
            int y = wsum[lane];
#pragma unroll
            for (int o = 1; o < 32; o <<= 1) {
                int t = __shfl_up_sync(0xffffffffu, y, o);
                if (lane >= o) y += t;
            }
            wsum[lane] = y;
        }
        __syncthreads();
        int incl = x + (w ? wsum[w - 1] : 0);
        if (i < n) {
            int ex = base + incl - v;
            rp[i] = ex;
            cur[i] = ex;
        }
        base += wsum[31];
        __syncthreads();
    }
    if (tid == 0) rp[n] = base;
}

__global__ void fill_edges(const int* __restrict__ src, const int* __restrict__ dst,
                           int* __restrict__ cur_sq, int* __restrict__ cur_mq,
                           int* __restrict__ col_sq, int* __restrict__ col_mq) {
    int e = blockIdx.x * blockDim.x + threadIdx.x;
    if (e < E_EDGES) {
        int s = src[e], d = dst[e];
        col_sq[atomicAdd(&cur_sq[d], 1)] = s;
        col_mq[atomicAdd(&cur_mq[s], 1)] = d;
    }
}

// ---------------- prep kernels ----------------
__global__ void split_weights(const float* __restrict__ lin_W,
                              const float* __restrict__ Wl_s, const float* __restrict__ Wr_s,
                              const float* __restrict__ Wl_m, const float* __restrict__ Wr_m,
                              __nv_bfloat16* __restrict__ wh, __nv_bfloat16* __restrict__ wl) {
    int i = blockIdx.x * blockDim.x + threadIdx.x;
    if (i < W_LIN_ELEMS) {
        float v = lin_W[i];
        float h = __bfloat162float(__float2bfloat16(v));
        wh[i] = __float2bfloat16(v);
        wl[i] = __float2bfloat16(v - h);
    } else if (i < W_TOT) {
        int j = i - W_LIN_ELEMS;
        int ld = j >> 15;            // (layer*2 + dir)
        int e = j & 32767;
        int r = e >> 8;              // 0..127 row
        int cc = e & 255;            // 0..255 col
        int part = cc >> 7;          // 0 = Wl, 1 = Wr
        int c = cc & 127;
        int layer = ld >> 1, dir = ld & 1;
        const float* srcm = dir ? (part ? Wr_m : Wl_m) : (part ? Wr_s : Wl_s);
        float v = srcm[(size_t)layer * HD * HD + r * HD + c];
        float h = __bfloat162float(__float2bfloat16(v));
        wh[i] = __float2bfloat16(v);
        wl[i] = __float2bfloat16(v - h);
    }
}

__global__ void split_sqx(const float* __restrict__ x,
                          __nv_bfloat16* __restrict__ xh, __nv_bfloat16* __restrict__ xl) {
    size_t i = (size_t)blockIdx.x * blockDim.x + threadIdx.x;
    if (i < (size_t)N_NODES * FIN) {
        float v = x[i];
        float h = __bfloat162float(__float2bfloat16(v));
        xh[i] = __float2bfloat16(v);
        xl[i] = __float2bfloat16(v - h);
    }
}

// user_emb -> xmq0 fp32 copy + root planes (buf0, mq region)
__global__ void init_mq(const float* __restrict__ user_emb, float* __restrict__ xmq0,
                        __nv_bfloat16* __restrict__ Ah, __nv_bfloat16* __restrict__ Al) {
    size_t i = (size_t)blockIdx.x * blockDim.x + threadIdx.x;
    if (i < (size_t)N_NODES * HD) {
        float v = user_emb[i];
        xmq0[i] = v;
        int r = (int)(i >> 7), c = (int)(i & 127);
        size_t o = (size_t)(MQ_OFF + r) * LDA2 + 128 + c;
        float h = __bfloat162float(__float2bfloat16(v));
        Ah[o] = __float2bfloat16(v);
        Al[o] = __float2bfloat16(v - h);
    }
}

// ---------------- dual mean aggregation: one warp per (dir, node) ----------------
__global__ void aggregate_dual(const float* __restrict__ xm, const float* __restrict__ xs,
                               const int* __restrict__ rp_sq, const int* __restrict__ col_sq,
                               const int* __restrict__ rp_mq, const int* __restrict__ col_mq,
                               __nv_bfloat16* __restrict__ Ah, __nv_bfloat16* __restrict__ Al) {
    int wid = (blockIdx.x * blockDim.x + threadIdx.x) >> 5;
    int lane = threadIdx.x & 31;
    if (wid >= 2 * N_NODES) return;
    bool dir = (wid >= N_NODES);
    int node = dir ? wid - N_NODES : wid;
    const int* rp = dir ? rp_mq : rp_sq;
    const int* col = dir ? col_mq : col_sq;
    const float* x = dir ? xs : xm;
    int beg = rp[node], end = rp[node + 1];
    float ax = 0.f, ay = 0.f, az = 0.f, aw = 0.f;
    int j = beg;
    for (; j + 4 <= end; j += 4) {
        int s0 = col[j], s1 = col[j + 1], s2 = col[j + 2], s3 = col[j + 3];
        float4 v0 = *(const float4*)&x[(size_t)s0 * HD + lane * 4];
        float4 v1 = *(const float4*)&x[(size_t)s1 * HD + lane * 4];
        float4 v2 = *(const float4*)&x[(size_t)s2 * HD + lane * 4];
        float4 v3 = *(const float4*)&x[(size_t)s3 * HD + lane * 4];
        ax += v0.x + v1.x + v2.x + v3.x;
        ay += v0.y + v1.y + v2.y + v3.y;
        az += v0.z + v1.z + v2.z + v3.z;
        aw += v0.w + v1.w + v2.w + v3.w;
    }
    for (; j < end; j++) {
        int s = col[j];
        float4 v = *(const float4*)&x[(size_t)s * HD + lane * 4];
        ax += v.x; ay += v.y; az += v.z; aw += v.w;
    }
    float inv = (end > beg) ? 1.0f / (float)(end - beg) : 0.f;
    float m0 = ax * inv, m1 = ay * inv, m2 = az * inv, m3 = aw * inv;
    float h0 = __bfloat162float(__float2bfloat16(m0));
    float h1 = __bfloat162float(__float2bfloat16(m1));
    float h2 = __bfloat162float(__float2bfloat16(m2));
    float h3 = __bfloat162float(__float2bfloat16(m3));
    size_t orow = (size_t)(dir ? MQ_OFF + node : node) * LDA2 + lane * 4;
    *(uint2*)&Ah[orow] = make_uint2(pack_bf2(m0, m1), pack_bf2(m2, m3));
    *(uint2*)&Al[orow] = make_uint2(pack_bf2(m0 - h0, m1 - h1), pack_bf2(m2 - h2, m3 - h3));
}

// ---------------- pipelined bf16 GEMM -------------------------------------
// C[local,128] = A[g,:kTot] (hi+lo planes) @ W[128,kTot]^T (hi+lo), 3-pass hi/lo.
// CTA tile 128x128; 8 warps 4(M)x2(N); K-chunk 32; 2-stage cp.async pipeline.
// dir select (weights/bias/C) by block row vs `split`.
#define SST 40
#define PLANE_B 10240      // 128 * 80
#define STAGE_B 40960      // 4 planes
#define SMEM_GEMM (2 * STAGE_B)

__global__ __launch_bounds__(256) void gemm_bf16(
    const __nv_bfloat16* __restrict__ Ah, const __nv_bfloat16* __restrict__ Al,
    int ldA, int kTot, int aRows,
    const __nv_bfloat16* __restrict__ Wh0, const __nv_bfloat16* __restrict__ Wl0,
    const __nv_bfloat16* __restrict__ Wh1, const __nv_bfloat16* __restrict__ Wl1,
    const float* __restrict__ bias0, const float* __restrict__ bias1,
    const float* __restrict__ addMat,
    float* __restrict__ C0, float* __restrict__ C1,
    __nv_bfloat16* __restrict__ rootH, __nv_bfloat16* __restrict__ rootL,
    int relu, int split) {
    extern __shared__ __align__(16) char smem[];
    const uint32_t sbase = smem_u32(smem);
    const int tid = threadIdx.x;
    const int wid = tid >> 5, lane = tid & 31;
    const int wm = wid & 3, wn = wid >> 2;
    const int blkRow0 = blockIdx.x * 128;
    const bool dir = (blkRow0 >= split);
    const int dirOff = dir ? split : 0;
    const __nv_bfloat16* Wh = dir ? Wh1 : Wh0;
    const __nv_bfloat16* Wl = dir ? Wl1 : Wl0;
    const float* bias = dir ? bias1 : bias0;
    float* C = dir ? C1 : C0;

    // loader: plane p (0=Ah,1=Al,2=Wh,3=Wl), 2 rows per thread, 4x16B per row
    const int p = tid >> 6;
    const int t = tid & 63;

    // ldmatrix lane addressing
    const int aRow = wm * 32 + (lane & 15);
    const int aColSeg = (lane >> 4) * 8;
    const int bRow = wn * 64 + ((lane >> 4) & 1) * 8 + (lane & 7);
    const int bColSeg = ((lane >> 3) & 1) * 8;

    float acc[2][8][4];
#pragma unroll
    for (int i = 0; i < 2; i++)
#pragma unroll
        for (int j = 0; j < 8; j++)
#pragma unroll
            for (int q = 0; q < 4; q++) acc[i][j][q] = 0.f;

    auto loadStage = [&](int st, int k0) {
        uint32_t db = sbase + st * STAGE_B + p * PLANE_B;
#pragma unroll
        for (int rr = 0; rr < 2; rr++) {
            int r = (t << 1) + rr;
            const __nv_bfloat16* gsrc;
            uint32_t bytes = 16;
            if (p < 2) {
                int grow = blkRow0 + r;
                gsrc = (p == 0 ? Ah : Al) + (size_t)grow * ldA + k0;
                if (grow >= aRows) bytes = 0;
            } else {
                gsrc = (p == 2 ? Wh : Wl) + (size_t)r * ldA + k0;
            }
            uint32_t d = db + r * 80;
#pragma unroll
            for (int q = 0; q < 4; q++)
                cp16(d + q * 16, (const char*)gsrc + q * 16, bytes);
        }
    };

    const int nCh = kTot >> 5;
    loadStage(0, 0);
    CP_COMMIT();
#pragma unroll 1
    for (int c = 0; c < nCh; c++) {
        if (c + 1 < nCh) {
            loadStage((c + 1) & 1, (c + 1) << 5);
            CP_COMMIT();
            CP_WAIT1();
        } else {
            CP_WAIT0();
        }
        __syncthreads();
        uint32_t base = sbase + (c & 1) * STAGE_B;
#pragma unroll
        for (int kstep = 0; kstep < 32; kstep += 16) {
            uint32_t ah[2][4], al[2][4];
#pragma unroll
            for (int mi = 0; mi < 2; mi++) {
                uint32_t aoff = (uint32_t)((aRow + mi * 16) * SST + kstep + aColSeg) * 2;
                ldsm_x4(ah[mi], base + aoff);
                ldsm_x4(al[mi], base + PLANE_B + aoff);
            }
#pragma unroll
            for (int pq = 0; pq < 4; pq++) {
                uint32_t boff = (uint32_t)((bRow + pq * 16) * SST + kstep + bColSeg) * 2;
                uint32_t bh[4], bl[4];
                ldsm_x4(bh, base + 2 * PLANE_B + boff);
                ldsm_x4(bl, base + 3 * PLANE_B + boff);
#pragma unroll
                for (int mi = 0; mi < 2; mi++) {
                    float* d0 = acc[mi][pq * 2 + 0];
                    float* d1 = acc[mi][pq * 2 + 1];
                    mma_bf16(d0, ah[mi], bh[0], bh[1]);
                    mma_bf16(d1, ah[mi], bh[2], bh[3]);
                    mma_bf16(d0, ah[mi], bl[0], bl[1]);
                    mma_bf16(d1, ah[mi], bl[2], bl[3]);
                    mma_bf16(d0, al[mi], bh[0], bh[1]);
                    mma_bf16(d1, al[mi], bh[2], bh[3]);
                }
            }
        }
        __syncthreads();
    }

    // ---- epilogue ----
    const int tileRowBase = wm * 32 + (lane >> 2);
    const int colBase = wn * 64 + (lane & 3) * 2;
#pragma unroll
    for (int mi = 0; mi < 2; mi++) {
#pragma unroll
        for (int h = 0; h < 2; h++) {
            int g = blkRow0 + tileRowBase + mi * 16 + h * 8;
            int lm = g - dirOff;
            if (lm >= N_NODES) continue;
            const float* amr = addMat ? &addMat[(size_t)lm * HD] : nullptr;
            float* cr = &C[(size_t)lm * HD];
            __nv_bfloat16* rh = rootH ? &rootH[(size_t)g * LDA2 + 128] : nullptr;
            __nv_bfloat16* rl = rootL ? &rootL[(size_t)g * LDA2 + 128] : nullptr;
#pragma unroll
            for (int nb = 0; nb < 8; nb++) {
                int cc = colBase + nb * 8;
                float v0 = acc[mi][nb][h * 2 + 0] + __ldg(&bias[cc]);
                float v1 = acc[mi][nb][h * 2 + 1] + __ldg(&bias[cc + 1]);
                if (amr) {
                    float2 a2 = *(const float2*)(amr + cc);
                    v0 += a2.x; v1 += a2.y;
                }
                if (relu) { v0 = fmaxf(v0, 0.f); v1 = fmaxf(v1, 0.f); }
                *(float2*)(cr + cc) = make_float2(v0, v1);
                if (rh) {
                    float h0 = __bfloat162float(__float2bfloat16(v0));
                    float h1 = __bfloat162float(__float2bfloat16(v1));
                    *(uint32_t*)(rh + cc) = pack_bf2(v0, v1);
                    *(uint32_t*)(rl + cc) = pack_bf2(v0 - h0, v1 - h1);
                }
            }
        }
    }
}

// ---------------- classifier: one warp per supervision edge ----------------
__global__ void classify(const float* __restrict__ xm, const float* __restrict__ xs,
                         const int* __restrict__ eli, float* __restrict__ out) {
    int wid = (blockIdx.x * blockDim.x + threadIdx.x) >> 5;
    int lane = threadIdx.x & 31;
    if (wid >= E_LABEL) return;
    int a = eli[wid];
    int b = eli[E_LABEL + wid];
    float4 u = *(const float4*)&xm[(size_t)a * HD + lane * 4];
    float4 v = *(const float4*)&xs[(size_t)b * HD + lane * 4];
    float s = u.x * v.x + u.y * v.y + u.z * v.z + u.w * v.w;
#pragma unroll
    for (int o = 16; o; o >>= 1) s += __shfl_xor_sync(0xffffffffu, s, o);
    if (lane == 0) out[wid] = s;
}

// ---------------- launch ----------------
extern "C" void kernel_launch(void* const* d_in, const int* in_sizes, int n_in,
                              void* d_out, int out_size) {
    const float* sq_x      = (const float*)d_in[2];
    const int*   edge_idx  = (const int*)d_in[3];
    const int*   eli       = (const int*)d_in[4];
    const float* user_emb  = (const float*)d_in[5];
    const float* movie_emb = (const float*)d_in[6];
    const float* lin_W     = (const float*)d_in[7];
    const float* lin_b     = (const float*)d_in[8];
    const float* Wl_s      = (const float*)d_in[9];
    const float* bl_s      = (const float*)d_in[10];
    const float* Wr_s      = (const float*)d_in[11];
    const float* Wl_m      = (const float*)d_in[12];
    const float* bl_m      = (const float*)d_in[13];
    const float* Wr_m      = (const float*)d_in[14];

    const int* src = edge_idx;
    const int* dst = edge_idx + E_EDGES;

    float *xmq, *xsq;
    __nv_bfloat16 *Ah, *Al, *sqxh, *sqxl, *wh, *wl;
    int *cnt_sq, *cnt_mq, *rp_sq, *rp_mq, *cur_sq, *cur_mq, *col_sq, *col_mq;
    cudaGetSymbolAddress((void**)&xmq, g_xmq);
    cudaGetSymbolAddress((void**)&xsq, g_xsq);
    cudaGetSymbolAddress((void**)&Ah, g_Ah);
    cudaGetSymbolAddress((void**)&Al, g_Al);
    cudaGetSymbolAddress((void**)&sqxh, g_sqxh);
    cudaGetSymbolAddress((void**)&sqxl, g_sqxl);
    cudaGetSymbolAddress((void**)&wh, g_wh);
    cudaGetSymbolAddress((void**)&wl, g_wl);
    cudaGetSymbolAddress((void**)&cnt_sq, g_cnt_sq);
    cudaGetSymbolAddress((void**)&cnt_mq, g_cnt_mq);
    cudaGetSymbolAddress((void**)&rp_sq, g_rp_sq);
    cudaGetSymbolAddress((void**)&rp_mq, g_rp_mq);
    cudaGetSymbolAddress((void**)&cur_sq, g_cur_sq);
    cudaGetSymbolAddress((void**)&cur_mq, g_cur_mq);
    cudaGetSymbolAddress((void**)&col_sq, g_col_sq);
    cudaGetSymbolAddress((void**)&col_mq, g_col_mq);

    cudaFuncSetAttribute(gemm_bf16, cudaFuncAttributeMaxDynamicSharedMemorySize, SMEM_GEMM);

    float* xmq0 = xmq;
    float* xmq1 = xmq + (size_t)N_NODES * HD;
    float* xsq0 = xsq;
    float* xsq1 = xsq + (size_t)N_NODES * HD;
    __nv_bfloat16* AhB[2] = {Ah, Ah + (size_t)TOT_ROWS * LDA2};
    __nv_bfloat16* AlB[2] = {Al, Al + (size_t)TOT_ROWS * LDA2};

    const int EB = (E_EDGES + 255) / 256;
    const int AGG_BLKS = (2 * N_NODES * 32 + 255) / 256;
    const int CLS_BLKS = (E_LABEL * 32 + 255) / 256;
    const int BIG = 1 << 30;

    // ---- CSR build ----
    cudaMemsetAsync(cnt_sq, 0, N_NODES * sizeof(int));
    cudaMemsetAsync(cnt_mq, 0, N_NODES * sizeof(int));
    count_edges<<<EB, 256>>>(src, dst, cnt_sq, cnt_mq);
    scan2<<<2, 1024>>>(cnt_sq, rp_sq, cur_sq, cnt_mq, rp_mq, cur_mq);
    fill_edges<<<EB, 256>>>(src, dst, cur_sq, cur_mq, col_sq, col_mq);

    // ---- prep: operand splits ----
    split_weights<<<(W_TOT + 255) / 256, 256>>>(lin_W, Wl_s, Wr_s, Wl_m, Wr_m, wh, wl);
    split_sqx<<<(int)(((size_t)N_NODES * FIN + 255) / 256), 256>>>(sq_x, sqxh, sqxl);
    init_mq<<<(N_NODES * HD + 255) / 256, 256>>>(user_emb, xmq0, AhB[0], AlB[0]);

    // ---- encoder: x_sq = sq_x @ lin_W^T + lin_b + movie_emb ----
    gemm_bf16<<<(N_NODES + 127) / 128, 256, SMEM_GEMM>>>(
        sqxh, sqxl, FIN, FIN, N_NODES,
        wh, wl, wh, wl, lin_b, lin_b, movie_emb,
        xsq0, xsq0, AhB[0], AlB[0], 0, BIG);

    float* xm = xmq0; float* xs = xsq0;
    float* xmn = xmq1; float* xsn = xsq1;
    for (int i = 0; i < NLAYERS; i++) {
        int relu = (i == 0) ? 1 : 0;
        int cur = i & 1, nxt = (i + 1) & 1;
        aggregate_dual<<<AGG_BLKS, 256>>>(xm, xs, rp_sq, col_sq, rp_mq, col_mq,
                                          AhB[cur], AlB[cur]);
        const __nv_bfloat16* wh0 = wh + W_LIN_ELEMS + (size_t)(i * 2 + 0) * W_LAYER_ELEMS;
        const __nv_bfloat16* wl0 = wl + W_LIN_ELEMS + (size_t)(i * 2 + 0) * W_LAYER_ELEMS;
        const __nv_bfloat16* wh1 = wh + W_LIN_ELEMS + (size_t)(i * 2 + 1) * W_LAYER_ELEMS;
        const __nv_bfloat16* wl1 = wl + W_LIN_ELEMS + (size_t)(i * 2 + 1) * W_LAYER_ELEMS;
        gemm_bf16<<<TOT_ROWS / 128, 256, SMEM_GEMM>>>(
            AhB[cur], AlB[cur], LDA2, LDA2, TOT_ROWS,
            wh0, wl0, wh1, wl1,
            bl_s + (size_t)i * HD, bl_m + (size_t)i * HD, nullptr,
            xsn, xmn, AhB[nxt], AlB[nxt], relu, MQ_OFF);
        float* tp;
        tp = xm; xm = xmn; xmn = tp;
        tp = xs; xs = xsn; xsn = tp;
    }

    classify<<<CLS_BLKS, 256>>>(xm, xs, eli, (float*)d_out);
}

// round 6
// speedup vs baseline: 1.2088x; 1.2088x over previous
#include <cuda_runtime.h>
#include <cuda_bf16.h>
#include <cstdint>
#include <cstddef>

#define N_NODES 50000
#define E_EDGES 600000
#define E_LABEL 200000
#define HD 128
#define FIN 768
#define NLAYERS 4
#define PAD_ROWS 50048              // 391 * 128
#define TOT_ROWS (2 * PAD_ROWS)     // 100096
#define LDA2 256                    // plane row: agg cols [0,128), root cols [128,256)
#define MQ_OFF PAD_ROWS
#define W_LIN_ELEMS (HD * FIN)
#define W_LAYER_ELEMS (HD * 256)
#define W_TOT (W_LIN_ELEMS + NLAYERS * 2 * W_LAYER_ELEMS)

// ---------------- device scratch ----------------
__device__ __nv_bfloat16 g_Ah[2 * (size_t)TOT_ROWS * LDA2];
__device__ __nv_bfloat16 g_Al[2 * (size_t)TOT_ROWS * LDA2];
__device__ __nv_bfloat16 g_wh[W_TOT];
__device__ __nv_bfloat16 g_wl[W_TOT];
__device__ int g_cnt_sq[N_NODES];
__device__ int g_cnt_mq[N_NODES];
__device__ int g_rp_sq[N_NODES + 1];
__device__ int g_rp_mq[N_NODES + 1];
__device__ int g_cur_sq[N_NODES];
__device__ int g_cur_mq[N_NODES];
__device__ int g_col_sq[E_EDGES];
__device__ int g_col_mq[E_EDGES];

// ================= helpers =================
__device__ __forceinline__ uint32_t smem_u32(const void* p) {
    uint32_t a;
    asm("{ .reg .u64 t; cvta.to.shared.u64 t, %1; cvt.u32.u64 %0, t; }" : "=r"(a) : "l"(p));
    return a;
}
__device__ __forceinline__ void ldsm_x4(uint32_t* r, uint32_t addr) {
    asm volatile("ldmatrix.sync.aligned.m8n8.x4.shared.b16 {%0,%1,%2,%3}, [%4];"
                 : "=r"(r[0]), "=r"(r[1]), "=r"(r[2]), "=r"(r[3]) : "r"(addr));
}
__device__ __forceinline__ void mma_bf16(float* d, const uint32_t* a, uint32_t b0, uint32_t b1) {
    asm volatile(
        "mma.sync.aligned.m16n8k16.row.col.f32.bf16.bf16.f32 "
        "{%0,%1,%2,%3},{%4,%5,%6,%7},{%8,%9},{%0,%1,%2,%3};"
        : "+f"(d[0]), "+f"(d[1]), "+f"(d[2]), "+f"(d[3])
        : "r"(a[0]), "r"(a[1]), "r"(a[2]), "r"(a[3]), "r"(b0), "r"(b1));
}
__device__ __forceinline__ uint32_t pack_bf2(float a, float b) {
    __nv_bfloat162 h = __floats2bfloat162_rn(a, b);
    return *reinterpret_cast<uint32_t*>(&h);
}
__device__ __forceinline__ float2 bf2f(uint32_t u) {
    __nv_bfloat162 h = *reinterpret_cast<__nv_bfloat162*>(&u);
    return __bfloat1622float2(h);
}
__device__ __forceinline__ void cp16(uint32_t dst, const void* src, uint32_t bytes) {
    asm volatile("cp.async.cg.shared.global [%0], [%1], 16, %2;"
                 :: "r"(dst), "l"(src), "r"(bytes));
}
#define CP_COMMIT() asm volatile("cp.async.commit_group;" ::: "memory")
#define CP_WAIT1() asm volatile("cp.async.wait_group 1;" ::: "memory")
#define CP_WAIT0() asm volatile("cp.async.wait_group 0;" ::: "memory")

// ---------------- CSR build ----------------
__global__ void count_edges(const int* __restrict__ src, const int* __restrict__ dst,
                            int* __restrict__ cnt_sq, int* __restrict__ cnt_mq) {
    int e = blockIdx.x * blockDim.x + threadIdx.x;
    if (e < E_EDGES) {
        atomicAdd(&cnt_sq[dst[e]], 1);
        atomicAdd(&cnt_mq[src[e]], 1);
    }
}

__global__ void scan2(const int* __restrict__ cntA, int* __restrict__ rpA, int* __restrict__ curA,
                      const int* __restrict__ cntB, int* __restrict__ rpB, int* __restrict__ curB) {
    const int* cnt = blockIdx.x ? cntB : cntA;
    int* rp  = blockIdx.x ? rpB  : rpA;
    int* cur = blockIdx.x ? curB : curA;
    const int n = N_NODES;
    __shared__ int wsum[32];
    int tid = threadIdx.x, lane = tid & 31, w = tid >> 5;
    int base = 0;
    for (int s = 0; s < n; s += 1024) {
        int i = s + tid;
        int v = (i < n) ? cnt[i] : 0;
        int x = v;
#pragma unroll
        for (int o = 1; o < 32; o <<= 1) {
            int t = __shfl_up_sync(0xffffffffu, x, o);
            if (lane >= o) x += t;
        }
        if (lane == 31) wsum[w] = x;
        __syncthreads();
        if (w == 0) {
            int y = wsum[lane];
#pragma unroll
            for (int o = 1; o < 32; o <<= 1) {
                int t = __shfl_up_sync(0xffffffffu, y, o);
                if (lane >= o) y += t;
            }
            wsum[lane] = y;
        }
        __syncthreads();
        int incl = x + (w ? wsum[w - 1] : 0);
        if (i < n) {
            int ex = base + incl - v;
            rp[i] = ex;
            cur[i] = ex;
        }
        base += wsum[31];
        __syncthreads();
    }
    if (tid == 0) rp[n] = base;
}

__global__ void fill_edges(const int* __restrict__ src, const int* __restrict__ dst,
                           int* __restrict__ cur_sq, int* __restrict__ cur_mq,
                           int* __restrict__ col_sq, int* __restrict__ col_mq) {
    int e = blockIdx.x * blockDim.x + threadIdx.x;
    if (e < E_EDGES) {
        int s = src[e], d = dst[e];
        col_sq[atomicAdd(&cur_sq[d], 1)] = s;
        col_mq[atomicAdd(&cur_mq[s], 1)] = d;
    }
}

// ---------------- prep ----------------
__global__ void split_weights(const float* __restrict__ lin_W,
                              const float* __restrict__ Wl_s, const float* __restrict__ Wr_s,
                              const float* __restrict__ Wl_m, const float* __restrict__ Wr_m,
                              __nv_bfloat16* __restrict__ wh, __nv_bfloat16* __restrict__ wl) {
    int i = blockIdx.x * blockDim.x + threadIdx.x;
    if (i < W_LIN_ELEMS) {
        float v = lin_W[i];
        float h = __bfloat162float(__float2bfloat16(v));
        wh[i] = __float2bfloat16(v);
        wl[i] = __float2bfloat16(v - h);
    } else if (i < W_TOT) {
        int j = i - W_LIN_ELEMS;
        int ld = j >> 15;
        int e = j & 32767;
        int r = e >> 8;
        int cc = e & 255;
        int part = cc >> 7;
        int c = cc & 127;
        int layer = ld >> 1, dir = ld & 1;
        const float* srcm = dir ? (part ? Wr_m : Wl_m) : (part ? Wr_s : Wl_s);
        float v = srcm[(size_t)layer * HD * HD + r * HD + c];
        float h = __bfloat162float(__float2bfloat16(v));
        wh[i] = __float2bfloat16(v);
        wl[i] = __float2bfloat16(v - h);
    }
}

// user_emb -> buf0 mq root planes
__global__ void init_mq(const float* __restrict__ user_emb,
                        __nv_bfloat16* __restrict__ Ah, __nv_bfloat16* __restrict__ Al) {
    size_t i = (size_t)blockIdx.x * blockDim.x + threadIdx.x;
    if (i < (size_t)N_NODES * HD) {
        float v = user_emb[i];
        int r = (int)(i >> 7), c = (int)(i & 127);
        size_t o = (size_t)(MQ_OFF + r) * LDA2 + 128 + c;
        float h = __bfloat162float(__float2bfloat16(v));
        Ah[o] = __float2bfloat16(v);
        Al[o] = __float2bfloat16(v - h);
    }
}

// ---------------- dual mean aggregation (planes in, planes out) ----------------
__global__ void aggregate_dual(const __nv_bfloat16* __restrict__ AhIn,
                               const __nv_bfloat16* __restrict__ AlIn,
                               const int* __restrict__ rp_sq, const int* __restrict__ col_sq,
                               const int* __restrict__ rp_mq, const int* __restrict__ col_mq,
                               __nv_bfloat16* __restrict__ AhOut, __nv_bfloat16* __restrict__ AlOut) {
    int wid = (blockIdx.x * blockDim.x + threadIdx.x) >> 5;
    int lane = threadIdx.x & 31;
    if (wid >= 2 * N_NODES) return;
    bool dir = (wid >= N_NODES);
    int node = dir ? wid - N_NODES : wid;
    const int* rp = dir ? rp_mq : rp_sq;
    const int* col = dir ? col_mq : col_sq;
    const int inOff = dir ? 0 : MQ_OFF;   // dir0: neighbors are mq rows; dir1: sq rows
    int beg = rp[node], end = rp[node + 1];
    float a0 = 0.f, a1 = 0.f, a2 = 0.f, a3 = 0.f;
    int j = beg;
    for (; j + 2 <= end; j += 2) {
        size_t r0 = (size_t)(inOff + col[j]) * LDA2 + 128 + lane * 4;
        size_t r1 = (size_t)(inOff + col[j + 1]) * LDA2 + 128 + lane * 4;
        uint2 h0 = *(const uint2*)&AhIn[r0];
        uint2 l0 = *(const uint2*)&AlIn[r0];
        uint2 h1 = *(const uint2*)&AhIn[r1];
        uint2 l1 = *(const uint2*)&AlIn[r1];
        float2 p0 = bf2f(h0.x), p1 = bf2f(h0.y), q0 = bf2f(l0.x), q1 = bf2f(l0.y);
        float2 p2 = bf2f(h1.x), p3 = bf2f(h1.y), q2 = bf2f(l1.x), q3 = bf2f(l1.y);
        a0 += p0.x + q0.x + p2.x + q2.x;
        a1 += p0.y + q0.y + p2.y + q2.y;
        a2 += p1.x + q1.x + p3.x + q3.x;
        a3 += p1.y + q1.y + p3.y + q3.y;
    }
    if (j < end) {
        size_t r0 = (size_t)(inOff + col[j]) * LDA2 + 128 + lane * 4;
        uint2 h0 = *(const uint2*)&AhIn[r0];
        uint2 l0 = *(const uint2*)&AlIn[r0];
        float2 p0 = bf2f(h0.x), p1 = bf2f(h0.y), q0 = bf2f(l0.x), q1 = bf2f(l0.y);
        a0 += p0.x + q0.x;
        a1 += p0.y + q0.y;
        a2 += p1.x + q1.x;
        a3 += p1.y + q1.y;
    }
    float inv = (end > beg) ? 1.0f / (float)(end - beg) : 0.f;
    a0 *= inv; a1 *= inv; a2 *= inv; a3 *= inv;
    float h0 = __bfloat162float(__float2bfloat16(a0));
    float h1 = __bfloat162float(__float2bfloat16(a1));
    float h2 = __bfloat162float(__float2bfloat16(a2));
    float h3 = __bfloat162float(__float2bfloat16(a3));
    size_t orow = (size_t)(dir ? MQ_OFF + node : node) * LDA2 + lane * 4;
    *(uint2*)&AhOut[orow] = make_uint2(pack_bf2(a0, a1), pack_bf2(a2, a3));
    *(uint2*)&AlOut[orow] = make_uint2(pack_bf2(a0 - h0, a1 - h1), pack_bf2(a2 - h2, a3 - h3));
}

// ================= encoder GEMM: fp32 A staged+converted in pipeline =================
// C = sq_x @ lin_W^T + lin_b + movie_emb -> root planes (buf0, sq region)
#define ENC_FA_SZ 18432                 // 128*36*4 (fp32 stage, stride 36)
#define ENC_AH (2 * ENC_FA_SZ)          // 36864
#define ENC_AL (ENC_AH + 10240)
#define ENC_WH0 (ENC_AL + 10240)
#define ENC_WL0 (ENC_WH0 + 10240)
#define ENC_WH1 (ENC_WL0 + 10240)
#define ENC_WL1 (ENC_WH1 + 10240)
#define ENC_SMEM (ENC_WL1 + 10240)      // 98304
#define SST 40

__global__ __launch_bounds__(256, 2) void gemm_enc(
    const float* __restrict__ A, const __nv_bfloat16* __restrict__ Wh,
    const __nv_bfloat16* __restrict__ Wl,
    const float* __restrict__ bias, const float* __restrict__ addMat,
    __nv_bfloat16* __restrict__ rootH, __nv_bfloat16* __restrict__ rootL) {
    extern __shared__ __align__(16) char smem[];
    const uint32_t sb = smem_u32(smem);
    const int tid = threadIdx.x, wid = tid >> 5, lane = tid & 31;
    const int wm = wid & 3, wn = wid >> 2;
    const int r = tid >> 1, p = tid & 1;
    const int mrow = blockIdx.x * 128 + r;
    const bool mvalid = (mrow < N_NODES);

    const int aRow = wm * 32 + (lane & 15);
    const int aColSeg = (lane >> 4) * 8;
    const int bRow = wn * 64 + ((lane >> 4) & 1) * 8 + (lane & 7);
    const int bColSeg = ((lane >> 3) & 1) * 8;

    float acc[2][8][4];
#pragma unroll
    for (int i = 0; i < 2; i++)
#pragma unroll
        for (int j = 0; j < 8; j++)
#pragma unroll
            for (int q = 0; q < 4; q++) acc[i][j][q] = 0.f;

    auto loadStage = [&](int st, int k0) {
        uint32_t fd = sb + st * ENC_FA_SZ + (uint32_t)(r * 36 + p * 16) * 4;
        const float* as = A + (size_t)mrow * FIN + k0 + p * 16;
        uint32_t ab = mvalid ? 16u : 0u;
        cp16(fd, as, ab); cp16(fd + 16, as + 4, ab);
        cp16(fd + 32, as + 8, ab); cp16(fd + 48, as + 12, ab);
        uint32_t whd = sb + (st ? ENC_WH1 : ENC_WH0) + r * 80 + p * 32;
        uint32_t wld = sb + (st ? ENC_WL1 : ENC_WL0) + r * 80 + p * 32;
        const __nv_bfloat16* wsh = Wh + (size_t)r * FIN + k0 + p * 16;
        const __nv_bfloat16* wsl = Wl + (size_t)r * FIN + k0 + p * 16;
        cp16(whd, wsh, 16); cp16(whd + 16, wsh + 8, 16);
        cp16(wld, wsl, 16); cp16(wld + 16, wsl + 8, 16);
    };

    const int nCh = FIN / 32;  // 24
    loadStage(0, 0);
    CP_COMMIT();
#pragma unroll 1
    for (int c = 0; c < nCh; c++) {
        if (c + 1 < nCh) {
            loadStage((c + 1) & 1, (c + 1) * 32);
            CP_COMMIT();
            CP_WAIT1();
        } else {
            CP_WAIT0();
        }
        __syncthreads();
        // convert fp32 stage -> hi/lo bf16 planes
        {
            const float* f = (const float*)(smem + (c & 1) * ENC_FA_SZ) + r * 36 + p * 16;
            __nv_bfloat16* ph = (__nv_bfloat16*)(smem + ENC_AH) + r * SST + p * 16;
            __nv_bfloat16* pl = (__nv_bfloat16*)(smem + ENC_AL) + r * SST + p * 16;
#pragma unroll
            for (int j = 0; j < 4; j++) {
                float4 v = *(const float4*)(f + j * 4);
                float hx = __bfloat162float(__float2bfloat16(v.x));
                float hy = __bfloat162float(__float2bfloat16(v.y));
                float hz = __bfloat162float(__float2bfloat16(v.z));
                float hw = __bfloat162float(__float2bfloat16(v.w));
                *(uint2*)(ph + j * 4) = make_uint2(pack_bf2(hx, hy), pack_bf2(hz, hw));
                *(uint2*)(pl + j * 4) =
                    make_uint2(pack_bf2(v.x - hx, v.y - hy), pack_bf2(v.z - hz, v.w - hw));
            }
        }
        __syncthreads();
        const uint32_t abh = sb + ENC_AH, abl = sb + ENC_AL;
        const uint32_t wbh = sb + ((c & 1) ? ENC_WH1 : ENC_WH0);
        const uint32_t wbl = sb + ((c & 1) ? ENC_WL1 : ENC_WL0);
#pragma unroll
        for (int kstep = 0; kstep < 32; kstep += 16) {
            uint32_t ah[2][4], al[2][4];
#pragma unroll
            for (int mi = 0; mi < 2; mi++) {
                uint32_t aoff = (uint32_t)((aRow + mi * 16) * SST + kstep + aColSeg) * 2;
                ldsm_x4(ah[mi], abh + aoff);
                ldsm_x4(al[mi], abl + aoff);
            }
#pragma unroll
            for (int pq = 0; pq < 4; pq++) {
                uint32_t boff = (uint32_t)((bRow + pq * 16) * SST + kstep + bColSeg) * 2;
                uint32_t bh[4], bl[4];
                ldsm_x4(bh, wbh + boff);
                ldsm_x4(bl, wbl + boff);
#pragma unroll
                for (int mi = 0; mi < 2; mi++) {
                    float* d0 = acc[mi][pq * 2 + 0];
                    float* d1 = acc[mi][pq * 2 + 1];
                    mma_bf16(d0, ah[mi], bh[0], bh[1]);
                    mma_bf16(d1, ah[mi], bh[2], bh[3]);
                    mma_bf16(d0, ah[mi], bl[0], bl[1]);
                    mma_bf16(d1, ah[mi], bl[2], bl[3]);
                    mma_bf16(d0, al[mi], bh[0], bh[1]);
                    mma_bf16(d1, al[mi], bh[2], bh[3]);
                }
            }
        }
        __syncthreads();
    }

    // epilogue: bias + movie_emb -> root planes only
    const int tileRowBase = wm * 32 + (lane >> 2);
    const int colBase = wn * 64 + (lane & 3) * 2;
#pragma unroll
    for (int mi = 0; mi < 2; mi++) {
#pragma unroll
        for (int h = 0; h < 2; h++) {
            int g = blockIdx.x * 128 + tileRowBase + mi * 16 + h * 8;
            if (g >= N_NODES) continue;
            const float* amr = &addMat[(size_t)g * HD];
            __nv_bfloat16* rh = &rootH[(size_t)g * LDA2 + 128];
            __nv_bfloat16* rl = &rootL[(size_t)g * LDA2 + 128];
#pragma unroll
            for (int nb = 0; nb < 8; nb++) {
                int cc = colBase + nb * 8;
                float2 a2 = *(const float2*)(amr + cc);
                float v0 = acc[mi][nb][h * 2 + 0] + __ldg(&bias[cc]) + a2.x;
                float v1 = acc[mi][nb][h * 2 + 1] + __ldg(&bias[cc + 1]) + a2.y;
                float h0 = __bfloat162float(__float2bfloat16(v0));
                float h1 = __bfloat162float(__float2bfloat16(v1));
                *(uint32_t*)(rh + cc) = pack_bf2(v0, v1);
                *(uint32_t*)(rl + cc) = pack_bf2(v0 - h0, v1 - h1);
            }
        }
    }
}

// ================= layer GEMM: pure bf16 planes, pipelined =================
#define PLANE_B 10240
#define STAGE_B 40960
#define SMEM_L (2 * STAGE_B)

__global__ __launch_bounds__(256, 2) void gemm_layer(
    const __nv_bfloat16* __restrict__ Ah, const __nv_bfloat16* __restrict__ Al,
    const __nv_bfloat16* __restrict__ Wh0, const __nv_bfloat16* __restrict__ Wl0,
    const __nv_bfloat16* __restrict__ Wh1, const __nv_bfloat16* __restrict__ Wl1,
    const float* __restrict__ bias0, const float* __restrict__ bias1,
    __nv_bfloat16* __restrict__ rootH, __nv_bfloat16* __restrict__ rootL,
    int relu) {
    extern __shared__ __align__(16) char smem[];
    const uint32_t sbase = smem_u32(smem);
    const int tid = threadIdx.x;
    const int wid = tid >> 5, lane = tid & 31;
    const int wm = wid & 3, wn = wid >> 2;
    const int blkRow0 = blockIdx.x * 128;
    const bool dir = (blkRow0 >= MQ_OFF);
    const int dirOff = dir ? MQ_OFF : 0;
    const __nv_bfloat16* Wh = dir ? Wh1 : Wh0;
    const __nv_bfloat16* Wl = dir ? Wl1 : Wl0;
    const float* bias = dir ? bias1 : bias0;

    const int p = tid >> 6;
    const int t = tid & 63;

    const int aRow = wm * 32 + (lane & 15);
    const int aColSeg = (lane >> 4) * 8;
    const int bRow = wn * 64 + ((lane >> 4) & 1) * 8 + (lane & 7);
    const int bColSeg = ((lane >> 3) & 1) * 8;

    float acc[2][8][4];
#pragma unroll
    for (int i = 0; i < 2; i++)
#pragma unroll
        for (int j = 0; j < 8; j++)
#pragma unroll
            for (int q = 0; q < 4; q++) acc[i][j][q] = 0.f;

    auto loadStage = [&](int st, int k0) {
        uint32_t db = sbase + st * STAGE_B + p * PLANE_B;
#pragma unroll
        for (int rr = 0; rr < 2; rr++) {
            int r = (t << 1) + rr;
            const __nv_bfloat16* gsrc;
            if (p < 2)
                gsrc = (p == 0 ? Ah : Al) + (size_t)(blkRow0 + r) * LDA2 + k0;
            else
                gsrc = (p == 2 ? Wh : Wl) + (size_t)r * LDA2 + k0;
            uint32_t d = db + r * 80;
#pragma unroll
            for (int q = 0; q < 4; q++)
                cp16(d + q * 16, (const char*)gsrc + q * 16, 16);
        }
    };

    const int nCh = LDA2 / 32;  // 8
    loadStage(0, 0);
    CP_COMMIT();
#pragma unroll 1
    for (int c = 0; c < nCh; c++) {
        if (c + 1 < nCh) {
            loadStage((c + 1) & 1, (c + 1) * 32);
            CP_COMMIT();
            CP_WAIT1();
        } else {
            CP_WAIT0();
        }
        __syncthreads();
        uint32_t base = sbase + (c & 1) * STAGE_B;
#pragma unroll
        for (int kstep = 0; kstep < 32; kstep += 16) {
            uint32_t ah[2][4], al[2][4];
#pragma unroll
            for (int mi = 0; mi < 2; mi++) {
                uint32_t aoff = (uint32_t)((aRow + mi * 16) * SST + kstep + aColSeg) * 2;
                ldsm_x4(ah[mi], base + aoff);
                ldsm_x4(al[mi], base + PLANE_B + aoff);
            }
#pragma unroll
            for (int pq = 0; pq < 4; pq++) {
                uint32_t boff = (uint32_t)((bRow + pq * 16) * SST + kstep + bColSeg) * 2;
                uint32_t bh[4], bl[4];
                ldsm_x4(bh, base + 2 * PLANE_B + boff);
                ldsm_x4(bl, base + 3 * PLANE_B + boff);
#pragma unroll
                for (int mi = 0; mi < 2; mi++) {
                    float* d0 = acc[mi][pq * 2 + 0];
                    float* d1 = acc[mi][pq * 2 + 1];
                    mma_bf16(d0, ah[mi], bh[0], bh[1]);
                    mma_bf16(d1, ah[mi], bh[2], bh[3]);
                    mma_bf16(d0, ah[mi], bl[0], bl[1]);
                    mma_bf16(d1, ah[mi], bl[2], bl[3]);
                    mma_bf16(d0, al[mi], bh[0], bh[1]);
                    mma_bf16(d1, al[mi], bh[2], bh[3]);
                }
            }
        }
        __syncthreads();
    }

    // epilogue -> root planes only
    const int tileRowBase = wm * 32 + (lane >> 2);
    const int colBase = wn * 64 + (lane & 3) * 2;
#pragma unroll
    for (int mi = 0; mi < 2; mi++) {
#pragma unroll
        for (int h = 0; h < 2; h++) {
            int g = blkRow0 + tileRowBase + mi * 16 + h * 8;
            if (g - dirOff >= N_NODES) continue;
            __nv_bfloat16* rh = &rootH[(size_t)g * LDA2 + 128];
            __nv_bfloat16* rl = &rootL[(size_t)g * LDA2 + 128];
#pragma unroll
            for (int nb = 0; nb < 8; nb++) {
                int cc = colBase + nb * 8;
                float v0 = acc[mi][nb][h * 2 + 0] + __ldg(&bias[cc]);
                float v1 = acc[mi][nb][h * 2 + 1] + __ldg(&bias[cc + 1]);
                if (relu) { v0 = fmaxf(v0, 0.f); v1 = fmaxf(v1, 0.f); }
                float h0 = __bfloat162float(__float2bfloat16(v0));
                float h1 = __bfloat162float(__float2bfloat16(v1));
                *(uint32_t*)(rh + cc) = pack_bf2(v0, v1);
                *(uint32_t*)(rl + cc) = pack_bf2(v0 - h0, v1 - h1);
            }
        }
    }
}

// ---------------- classifier (planes in) ----------------
__global__ void classify(const __nv_bfloat16* __restrict__ Ah,
                         const __nv_bfloat16* __restrict__ Al,
                         const int* __restrict__ eli, float* __restrict__ out) {
    int wid = (blockIdx.x * blockDim.x + threadIdx.x) >> 5;
    int lane = threadIdx.x & 31;
    if (wid >= E_LABEL) return;
    int a = eli[wid];
    int b = eli[E_LABEL + wid];
    size_t ra = (size_t)(MQ_OFF + a) * LDA2 + 128 + lane * 4;
    size_t rb = (size_t)b * LDA2 + 128 + lane * 4;
    uint2 uh = *(const uint2*)&Ah[ra];
    uint2 ul = *(const uint2*)&Al[ra];
    uint2 vh = *(const uint2*)&Ah[rb];
    uint2 vl = *(const uint2*)&Al[rb];
    float2 u0 = bf2f(uh.x), u1 = bf2f(uh.y), x0 = bf2f(ul.x), x1 = bf2f(ul.y);
    float2 v0 = bf2f(vh.x), v1 = bf2f(vh.y), y0 = bf2f(vl.x), y1 = bf2f(vl.y);
    float s = (u0.x + x0.x) * (v0.x + y0.x) + (u0.y + x0.y) * (v0.y + y0.y) +
              (u1.x + x1.x) * (v1.x + y1.x) + (u1.y + x1.y) * (v1.y + y1.y);
#pragma unroll
    for (int o = 16; o; o >>= 1) s += __shfl_xor_sync(0xffffffffu, s, o);
    if (lane == 0) out[wid] = s;
}

// ---------------- launch ----------------
extern "C" void kernel_launch(void* const* d_in, const int* in_sizes, int n_in,
                              void* d_out, int out_size) {
    const float* sq_x      = (const float*)d_in[2];
    const int*   edge_idx  = (const int*)d_in[3];
    const int*   eli       = (const int*)d_in[4];
    const float* user_emb  = (const float*)d_in[5];
    const float* movie_emb = (const float*)d_in[6];
    const float* lin_W     = (const float*)d_in[7];
    const float* lin_b     = (const float*)d_in[8];
    const float* Wl_s      = (const float*)d_in[9];
    const float* bl_s      = (const float*)d_in[10];
    const float* Wr_s      = (const float*)d_in[11];
    const float* Wl_m      = (const float*)d_in[12];
    const float* bl_m      = (const float*)d_in[13];
    const float* Wr_m      = (const float*)d_in[14];

    const int* src = edge_idx;
    const int* dst = edge_idx + E_EDGES;

    __nv_bfloat16 *Ah, *Al, *wh, *wl;
    int *cnt_sq, *cnt_mq, *rp_sq, *rp_mq, *cur_sq, *cur_mq, *col_sq, *col_mq;
    cudaGetSymbolAddress((void**)&Ah, g_Ah);
    cudaGetSymbolAddress((void**)&Al, g_Al);
    cudaGetSymbolAddress((void**)&wh, g_wh);
    cudaGetSymbolAddress((void**)&wl, g_wl);
    cudaGetSymbolAddress((void**)&cnt_sq, g_cnt_sq);
    cudaGetSymbolAddress((void**)&cnt_mq, g_cnt_mq);
    cudaGetSymbolAddress((void**)&rp_sq, g_rp_sq);
    cudaGetSymbolAddress((void**)&rp_mq, g_rp_mq);
    cudaGetSymbolAddress((void**)&cur_sq, g_cur_sq);
    cudaGetSymbolAddress((void**)&cur_mq, g_cur_mq);
    cudaGetSymbolAddress((void**)&col_sq, g_col_sq);
    cudaGetSymbolAddress((void**)&col_mq, g_col_mq);

    cudaFuncSetAttribute(gemm_enc, cudaFuncAttributeMaxDynamicSharedMemorySize, ENC_SMEM);
    cudaFuncSetAttribute(gemm_layer, cudaFuncAttributeMaxDynamicSharedMemorySize, SMEM_L);

    __nv_bfloat16* AhB[2] = {Ah, Ah + (size_t)TOT_ROWS * LDA2};
    __nv_bfloat16* AlB[2] = {Al, Al + (size_t)TOT_ROWS * LDA2};

    const int EB = (E_EDGES + 255) / 256;
    const int AGG_BLKS = (2 * N_NODES * 32 + 255) / 256;
    const int CLS_BLKS = (E_LABEL * 32 + 255) / 256;

    // ---- CSR ----
    cudaMemsetAsync(cnt_sq, 0, N_NODES * sizeof(int));
    cudaMemsetAsync(cnt_mq, 0, N_NODES * sizeof(int));
    count_edges<<<EB, 256>>>(src, dst, cnt_sq, cnt_mq);
    scan2<<<2, 1024>>>(cnt_sq, rp_sq, cur_sq, cnt_mq, rp_mq, cur_mq);
    fill_edges<<<EB, 256>>>(src, dst, cur_sq, cur_mq, col_sq, col_mq);

    // ---- prep ----
    split_weights<<<(W_TOT + 255) / 256, 256>>>(lin_W, Wl_s, Wr_s, Wl_m, Wr_m, wh, wl);
    init_mq<<<(N_NODES * HD + 255) / 256, 256>>>(user_emb, AhB[0], AlB[0]);

    // ---- encoder ----
    gemm_enc<<<(N_NODES + 127) / 128, 256, ENC_SMEM>>>(
        sq_x, wh, wl, lin_b, movie_emb, AhB[0], AlB[0]);

    // ---- layers ----
    for (int i = 0; i < NLAYERS; i++) {
        int cur = i & 1, nxt = (i + 1) & 1;
        aggregate_dual<<<AGG_BLKS, 256>>>(AhB[cur], AlB[cur], rp_sq, col_sq, rp_mq, col_mq,
                                          AhB[cur], AlB[cur]);
        const __nv_bfloat16* wh0 = wh + W_LIN_ELEMS + (size_t)(i * 2 + 0) * W_LAYER_ELEMS;
        const __nv_bfloat16* wl0 = wl + W_LIN_ELEMS + (size_t)(i * 2 + 0) * W_LAYER_ELEMS;
        const __nv_bfloat16* wh1 = wh + W_LIN_ELEMS + (size_t)(i * 2 + 1) * W_LAYER_ELEMS;
        const __nv_bfloat16* wl1 = wl + W_LIN_ELEMS + (size_t)(i * 2 + 1) * W_LAYER_ELEMS;
        gemm_layer<<<TOT_ROWS / 128, 256, SMEM_L>>>(
            AhB[cur], AlB[cur], wh0, wl0, wh1, wl1,
            bl_s + (size_t)i * HD, bl_m + (size_t)i * HD,
            AhB[nxt], AlB[nxt], (i == 0) ? 1 : 0);
    }

    // ---- classifier (final roots in buf0) ----
    classify<<<CLS_BLKS, 256>>>(AhB[0], AlB[0], eli, (float*)d_out);
}